// round 8
// baseline (speedup 1.0000x reference)
#include <cuda_runtime.h>
#include <cstdint>

#define N_ENT   100000
#define N_DRUG  2000
#define N_REL   51
#define N_EDGE  1000000
#define DIM     64
#define BUCKET  64          // per-head capacity; Poisson(10) max over 100K ~35

// Device-global scratch (zero-initialized at module load).
// Rel tables have a leading ZERO row (row 0 never written): pad edge slots
// are packed-0 -> gather ent[0] (valid row) * rel[0] (zeros) -> contribute 0.
__device__ float    g_entA [N_ENT * DIM];
__device__ float    g_entB [N_ENT * DIM];
__device__ float    g_rel0z[(N_REL + 1) * DIM];   // fp32 rel0, shifted +1
__device__ float    g_relnz[(N_REL + 1) * DIM];   // fp32 norm(rel0), shifted +1
__device__ int      g_cnt  [N_ENT];
__device__ unsigned g_edges[N_ENT * BUCKET];      // packed: tail | (rel+1)<<17

// ---------------------------------------------------------------------------
// Bucket fill: 8 edges per thread (8 independent ATOMG.ADDs in flight)
// ---------------------------------------------------------------------------
__global__ void fill_kernel(const int* __restrict__ eidx,
                            const int* __restrict__ etype) {
    int base = (blockIdx.x * blockDim.x + threadIdx.x) * 8;
    #pragma unroll
    for (int k = 0; k < 8; k++) {
        int e = base + k;
        if (e < N_EDGE) {
            int h  = eidx[e];
            int tl = eidx[N_EDGE + e];
            int r  = etype[e];
            int pos = atomicAdd(&g_cnt[h], 1);
            if (pos < BUCKET)
                g_edges[(long long)h * BUCKET + pos] =
                    (unsigned)tl | ((unsigned)(r + 1) << 17);
        }
    }
}

// ---------------------------------------------------------------------------
// Relations (once): out_rel = rel0 + 3*normalize(rel0) (norm is idempotent);
// fill shifted fp32 tables g_rel0z / g_relnz rows 1..N_REL (row 0 stays 0).
// ---------------------------------------------------------------------------
__global__ void rel_kernel(const float* __restrict__ rel0,
                           float* __restrict__ out_rel) {
    int row  = blockIdx.x;
    int lane = threadIdx.x;

    float2 v = reinterpret_cast<const float2*>(rel0)[row * 32 + lane];
    float ss = v.x * v.x + v.y * v.y;
    #pragma unroll
    for (int o = 16; o > 0; o >>= 1)
        ss += __shfl_xor_sync(0xFFFFFFFFu, ss, o);

    float inv = 1.0f / fmaxf(sqrtf(ss), 1e-12f);
    float2 n = { v.x * inv, v.y * inv };

    reinterpret_cast<float2*>(g_rel0z)[(row + 1) * 32 + lane] = v;
    reinterpret_cast<float2*>(g_relnz)[(row + 1) * 32 + lane] = n;

    float2 o2 = { v.x + 3.0f * n.x, v.y + 3.0f * n.y };
    reinterpret_cast<float2*>(out_rel)[row * 32 + lane] = o2;
}

// ---------------------------------------------------------------------------
// Fused gather + L2-normalize. One warp per row; HALF-WARP PER EDGE:
// lanes 0-15 process edge i, lanes 16-31 process edge i+1 (float4 per lane,
// LDG.128). One shfl serves two edges. Unmasked loop (pad slots hit the rel
// zero-row). Cross-half combine via shfl_xor(16) before the norm reduction.
//   final_hop=0: dst[row] = n
//   final_hop=1: out_ent = base + entA + entB + n ; ditto drug rows
// ---------------------------------------------------------------------------
__global__ void gather_kernel(const ulonglong2* __restrict__ ent,
                              const ulonglong2* __restrict__ rel,
                              float4*           __restrict__ dst,
                              const float4*     __restrict__ base_ent,
                              const float4*     __restrict__ base_drug,
                              float4*           __restrict__ out_ent,
                              float4*           __restrict__ out_drug,
                              int final_hop) {
    int row  = (blockIdx.x * blockDim.x + threadIdx.x) >> 5;
    int lane = threadIdx.x & 31;
    if (row >= N_ENT) return;

    int sub = lane >> 4;        // which edge of the pair this half-warp owns
    int q   = lane & 15;        // float4 index within the 64-dim row

    int deg = g_cnt[row];
    if (deg > BUCKET) deg = BUCKET;
    long long ebase = (long long)row * BUCKET;
    unsigned myp = g_edges[ebase + lane];   // coalesced: row's first 32 edges

    unsigned long long accA = 0ull, accB = 0ull;   // packed f32x2 accumulators
    int dmain = deg < 32 ? deg : 32;
    int slots = (dmain + 3) & ~3;                  // 4 edges / iteration

    for (int i = 0; i < slots; i += 4) {
        unsigned pa = __shfl_sync(0xFFFFFFFFu, myp, i + sub);
        unsigned pb = __shfl_sync(0xFFFFFFFFu, myp, i + 2 + sub);
        ulonglong2 a0 = ent[(pa & 0x1FFFFu) * 16 + q];
        ulonglong2 b0 = rel[(pa >> 17)      * 16 + q];
        ulonglong2 a1 = ent[(pb & 0x1FFFFu) * 16 + q];
        ulonglong2 b1 = rel[(pb >> 17)      * 16 + q];
        asm("fma.rn.f32x2 %0, %1, %2, %0;" : "+l"(accA) : "l"(a0.x), "l"(b0.x));
        asm("fma.rn.f32x2 %0, %1, %2, %0;" : "+l"(accB) : "l"(a0.y), "l"(b0.y));
        asm("fma.rn.f32x2 %0, %1, %2, %0;" : "+l"(accA) : "l"(a1.x), "l"(b1.x));
        asm("fma.rn.f32x2 %0, %1, %2, %0;" : "+l"(accB) : "l"(a1.y), "l"(b1.y));
    }

    // ultra-rare tail (deg > 32): sub==0 half only (avoid double count)
    for (int t = 32; t < deg; t++) {
        if (sub == 0) {
            unsigned p = g_edges[ebase + t];
            ulonglong2 a = ent[(p & 0x1FFFFu) * 16 + q];
            ulonglong2 b = rel[(p >> 17)      * 16 + q];
            asm("fma.rn.f32x2 %0, %1, %2, %0;" : "+l"(accA) : "l"(a.x), "l"(b.x));
            asm("fma.rn.f32x2 %0, %1, %2, %0;" : "+l"(accB) : "l"(a.y), "l"(b.y));
        }
    }

    float f0, f1, f2, f3;
    asm("mov.b64 {%0, %1}, %2;" : "=f"(f0), "=f"(f1) : "l"(accA));
    asm("mov.b64 {%0, %1}, %2;" : "=f"(f2), "=f"(f3) : "l"(accB));

    // combine the two half-warps (same q, different edge subsets)
    f0 += __shfl_xor_sync(0xFFFFFFFFu, f0, 16);
    f1 += __shfl_xor_sync(0xFFFFFFFFu, f1, 16);
    f2 += __shfl_xor_sync(0xFFFFFFFFu, f2, 16);
    f3 += __shfl_xor_sync(0xFFFFFFFFu, f3, 16);

    float ss = f0 * f0 + f1 * f1 + f2 * f2 + f3 * f3;
    #pragma unroll
    for (int o = 8; o > 0; o >>= 1)
        ss += __shfl_xor_sync(0xFFFFFFFFu, ss, o);

    float inv = 1.0f / fmaxf(sqrtf(ss), 1e-12f);
    float4 n = make_float4(f0 * inv, f1 * inv, f2 * inv, f3 * inv);

    if (sub == 0) {
        long long idx = (long long)row * 16 + q;
        if (!final_hop) {
            dst[idx] = n;
        } else {
            float4 a1v = reinterpret_cast<const float4*>(g_entA)[idx];
            float4 a2v = reinterpret_cast<const float4*>(g_entB)[idx];
            float sx = a1v.x + a2v.x + n.x;
            float sy = a1v.y + a2v.y + n.y;
            float sz = a1v.z + a2v.z + n.z;
            float sw = a1v.w + a2v.w + n.w;

            float4 e0 = base_ent[idx];
            out_ent[idx] = make_float4(e0.x + sx, e0.y + sy,
                                       e0.z + sz, e0.w + sw);
            if (row < N_DRUG) {
                float4 d0 = base_drug[idx];
                out_drug[idx] = make_float4(d0.x + sx, d0.y + sy,
                                            d0.z + sz, d0.w + sw);
            }
        }
    }
}

// ---------------------------------------------------------------------------
extern "C" void kernel_launch(void* const* d_in, const int* in_sizes, int n_in,
                              void* d_out, int out_size) {
    const float* ent0  = (const float*)d_in[0];
    const float* drug0 = (const float*)d_in[1];
    const float* rel0  = (const float*)d_in[2];
    const int*   eidx  = (const int*)d_in[3];
    const int*   etype = (const int*)d_in[4];

    float* out      = (float*)d_out;
    float* out_ent  = out;
    float* out_drug = out + (size_t)N_ENT * DIM;
    float* out_rel  = out + (size_t)(N_ENT + N_DRUG) * DIM;

    void *pA, *pB, *pR0, *pRN, *pC;
    cudaGetSymbolAddress(&pA,  g_entA);
    cudaGetSymbolAddress(&pB,  g_entB);
    cudaGetSymbolAddress(&pR0, g_rel0z);
    cudaGetSymbolAddress(&pRN, g_relnz);
    cudaGetSymbolAddress(&pC,  g_cnt);

    // CSR-bucket build + relation tables
    cudaMemsetAsync(pC, 0, N_ENT * sizeof(int), 0);
    fill_kernel<<<(N_EDGE / 8 + 255) / 256, 256>>>(eidx, etype);
    rel_kernel<<<N_REL, 32>>>(rel0, out_rel);

    const int blocks = (N_ENT * 32 + 255) / 256;

    // hop 0: ent0 * rel0 -> entA
    gather_kernel<<<blocks, 256>>>(
        (const ulonglong2*)ent0, (const ulonglong2*)pR0, (float4*)pA,
        nullptr, nullptr, nullptr, nullptr, 0);
    // hop 1: entA * norm(rel) -> entB
    gather_kernel<<<blocks, 256>>>(
        (const ulonglong2*)pA, (const ulonglong2*)pRN, (float4*)pB,
        nullptr, nullptr, nullptr, nullptr, 0);
    // hop 2 (final): entB * norm(rel) -> n3; out = base + entA + entB + n3
    gather_kernel<<<blocks, 256>>>(
        (const ulonglong2*)pB, (const ulonglong2*)pRN, nullptr,
        (const float4*)ent0, (const float4*)drug0,
        (float4*)out_ent, (float4*)out_drug, 1);
}